// round 1
// baseline (speedup 1.0000x reference)
#include <cuda_runtime.h>
#include <math.h>
#include <stdint.h>

// ---------------- problem constants ----------------
#define BSZ   2
#define L_SEQ 4097
#define NROWS (BSZ * L_SEQ)      // 8194
#define DM    256                 // d_model
#define DI    512                 // d_inner
#define DS    16                  // d_state
#define CHUNK 128
#define NCH   33                  // ceil(4097/128)
#define NXX   (NROWS * DM)        // 2,097,664
#define EPSF  1e-5f

// ---------------- scratch (static device globals; no runtime alloc) ------
__device__ float d_E[(size_t)BSZ * 1024 * 1024];        // expand GEMM out
__device__ float d_xx[(size_t)NROWS * DM];              // sequence activations
__device__ float d_xz[(size_t)NROWS * 1024];            // in_proj out
__device__ float d_xi[(size_t)NROWS * DI];              // conv+silu out
__device__ float d_dbc[(size_t)NROWS * 48];             // x_proj out
__device__ float d_del[(size_t)NROWS * DI];             // delta
__device__ float d_y[(size_t)NROWS * DI];               // gated scan out
__device__ float d_Aneg[DI * DS];
__device__ float d_Aagg[(size_t)BSZ * DI * NCH * DS];
__device__ float d_Hagg[(size_t)BSZ * DI * NCH * DS];
__device__ float d_Hst [(size_t)BSZ * DI * NCH * DS];
__device__ float d_pS[128 * DM];
__device__ float d_pQ[128 * DM];
__device__ float d_alpha[DM];
__device__ float d_beta[DM];

// ---------------- fast math (FMA-only exp; avoids MUFU throughput wall) --
static __device__ __forceinline__ float fast_exp(float x) {
    float y = x * 1.4426950408889634f;          // log2(e)
    y = fminf(fmaxf(y, -125.0f), 125.0f);
    float k = rintf(y);
    float g = (y - k) * 0.6931471805599453f;    // |g| <= 0.3466
    float p = 1.3888889e-3f;                    // 1/720
    p = fmaf(p, g, 8.3333333e-3f);              // 1/120
    p = fmaf(p, g, 4.1666667e-2f);              // 1/24
    p = fmaf(p, g, 1.6666667e-1f);              // 1/6
    p = fmaf(p, g, 0.5f);
    p = fmaf(p, g, 1.0f);
    p = fmaf(p, g, 1.0f);
    int ki = (int)k;
    float sc = __int_as_float((ki + 127) << 23);
    return p * sc;
}
static __device__ __forceinline__ float sigm(float x) {
    return 1.0f / (1.0f + fast_exp(-x));
}

// ---------------- generic SGEMM: C[M,N] = A[M,K] @ W[N,K]^T --------------
// 64x64 tile, 256 threads, 4x4 micro-tile, K % 16 == 0 required.
__global__ __launch_bounds__(256) void sgemm_tn(
    const float* __restrict__ A, const float* __restrict__ W,
    float* __restrict__ C, int M, int N, int K)
{
    __shared__ float As[16][64];
    __shared__ float Ws[16][64];
    int tid = threadIdx.x;
    int tx = tid & 15, ty = tid >> 4;
    int row0 = blockIdx.y * 64, col0 = blockIdx.x * 64;
    float acc[4][4];
#pragma unroll
    for (int i = 0; i < 4; i++)
#pragma unroll
        for (int j = 0; j < 4; j++) acc[i][j] = 0.0f;

    int lr = tid >> 2;            // 0..63
    int lk = (tid & 3) * 4;       // 0,4,8,12

    for (int kc = 0; kc < K; kc += 16) {
        float4 va = make_float4(0.f, 0.f, 0.f, 0.f);
        if (row0 + lr < M)
            va = *reinterpret_cast<const float4*>(A + (size_t)(row0 + lr) * K + kc + lk);
        As[lk + 0][lr] = va.x; As[lk + 1][lr] = va.y;
        As[lk + 2][lr] = va.z; As[lk + 3][lr] = va.w;
        float4 vw = make_float4(0.f, 0.f, 0.f, 0.f);
        if (col0 + lr < N)
            vw = *reinterpret_cast<const float4*>(W + (size_t)(col0 + lr) * K + kc + lk);
        Ws[lk + 0][lr] = vw.x; Ws[lk + 1][lr] = vw.y;
        Ws[lk + 2][lr] = vw.z; Ws[lk + 3][lr] = vw.w;
        __syncthreads();
#pragma unroll
        for (int kk = 0; kk < 16; kk++) {
            float a[4], w[4];
            *reinterpret_cast<float4*>(a) = *reinterpret_cast<const float4*>(&As[kk][ty * 4]);
            *reinterpret_cast<float4*>(w) = *reinterpret_cast<const float4*>(&Ws[kk][tx * 4]);
#pragma unroll
            for (int i = 0; i < 4; i++)
#pragma unroll
                for (int j = 0; j < 4; j++)
                    acc[i][j] = fmaf(a[i], w[j], acc[i][j]);
        }
        __syncthreads();
    }
#pragma unroll
    for (int i = 0; i < 4; i++) {
        int r = row0 + ty * 4 + i;
        if (r < M) {
#pragma unroll
            for (int j = 0; j < 4; j++) {
                int c = col0 + tx * 4 + j;
                if (c < N) C[(size_t)r * N + c] = acc[i][j];
            }
        }
    }
}

// ---------------- expand: LN over 256 + spatial scatter + skip -----------
// one block per (source token, quadrant): 2048*4 = 8192 blocks, 256 threads
__global__ void expand_ln(const float* __restrict__ skip,
                          const float* __restrict__ ln_g,
                          const float* __restrict__ ln_b)
{
    int idx = blockIdx.x;
    int q = idx & 3;            // s1*2 + s2
    int src = idx >> 2;         // b*1024 + t*256 + n
    int b = src >> 10;
    int rowb = src & 1023;
    int t = rowb >> 8;
    int n = rowb & 255;
    int hh = n >> 4, ww = n & 15;
    int s1 = q >> 1, s2 = q & 1;
    int p = ((hh * 2 + s1) * 16 + ww) * 2 + s2;
    int l = 1 + t * 1024 + p;
    int tid = threadIdx.x;

    float v = d_E[(size_t)src * 1024 + q * 256 + tid];

    __shared__ float red[256];
    red[tid] = v; __syncthreads();
    for (int s = 128; s > 0; s >>= 1) {
        if (tid < s) red[tid] += red[tid + s];
        __syncthreads();
    }
    float mu = red[0] * (1.0f / 256.0f);
    __syncthreads();
    float dv = v - mu;
    red[tid] = dv * dv; __syncthreads();
    for (int s = 128; s > 0; s >>= 1) {
        if (tid < s) red[tid] += red[tid + s];
        __syncthreads();
    }
    float var = red[0] * (1.0f / 256.0f);
    float outv = dv * (1.0f / sqrtf(var + EPSF)) * ln_g[tid] + ln_b[tid];
    size_t grow = (size_t)(b * L_SEQ + l);
    d_xx[grow * DM + tid] = outv + skip[grow * DM + tid];
}

// ---------------- cls token: proj + bias + skip --------------------------
__global__ void cls_kernel(const float* __restrict__ x,
                           const float* __restrict__ cls_w,
                           const float* __restrict__ cls_b,
                           const float* __restrict__ skip)
{
    int b = blockIdx.x;
    int c = threadIdx.x;
    const float* xr = x + (size_t)b * 1025 * 512;   // row 0 of batch b
    float s = cls_b[c];
    for (int k = 0; k < 512; k++) s = fmaf(xr[k], cls_w[(size_t)c * 512 + k], s);
    size_t grow = (size_t)b * L_SEQ;
    d_xx[grow * DM + c] = s + skip[grow * DM + c];
}

// ---------------- depthwise causal conv4 + silu --------------------------
__global__ void conv_silu(const float* __restrict__ cw, const float* __restrict__ cb)
{
    int idx = blockIdx.x * blockDim.x + threadIdx.x;
    if (idx >= NROWS * DI) return;
    int row = idx >> 9;           // global row b*L+l
    int d = idx & 511;
    int b = row / L_SEQ;
    int l = row - b * L_SEQ;
    float acc = cb[d];
#pragma unroll
    for (int k = 0; k < 4; k++) {
        int ls = l + k - 3;
        if (ls >= 0)
            acc = fmaf(cw[d * 4 + k], d_xz[(size_t)(b * L_SEQ + ls) * 1024 + d], acc);
    }
    d_xi[(size_t)row * DI + d] = acc * sigm(acc);
}

// ---------------- delta = softplus(dt @ Wdt^T + bdt) ---------------------
__global__ void delta_kernel(const float* __restrict__ Wdt, const float* __restrict__ bdt)
{
    int row = blockIdx.x;
    int dd = threadIdx.x;
    __shared__ float dt[16];
    if (dd < 16) dt[dd] = d_dbc[(size_t)row * 48 + dd];
    __syncthreads();
    float s = bdt[dd];
#pragma unroll
    for (int r = 0; r < 16; r++) s = fmaf(dt[r], Wdt[dd * 16 + r], s);
    float del = (s > 20.0f) ? s : log1pf(fast_exp(s));
    d_del[(size_t)row * DI + dd] = del;
}

// ---------------- A = -exp(A_log) ----------------------------------------
__global__ void prep_aneg(const float* __restrict__ Alog)
{
    int i = blockIdx.x * blockDim.x + threadIdx.x;
    if (i < DI * DS) d_Aneg[i] = -expf(Alog[i]);
}

// ---------------- chunked scan phase 1: local scan, aggregates -----------
// grid: (b*NCH + c)*4 + dq blocks of 128 threads; thread = one d, 16 states
__global__ __launch_bounds__(128) void scan_p1()
{
    int blk = blockIdx.x;
    int dq = blk & 3;
    int rest = blk >> 2;
    int c = rest % NCH;
    int b = rest / NCH;
    int d = dq * 128 + threadIdx.x;
    int t0 = c * CHUNK;
    int tlen = min(CHUNK, L_SEQ - t0);

    __shared__ float Bsh[CHUNK * DS];
    for (int i = threadIdx.x; i < tlen * DS; i += blockDim.x) {
        int t = i >> 4, n = i & 15;
        Bsh[i] = d_dbc[(size_t)(b * L_SEQ + t0 + t) * 48 + 16 + n];
    }
    __syncthreads();

    float A[DS], h[DS], ap[DS];
#pragma unroll
    for (int n = 0; n < DS; n++) {
        A[n] = d_Aneg[d * DS + n]; h[n] = 0.0f; ap[n] = 1.0f;
    }
    const float* dptr = d_del + (size_t)(b * L_SEQ + t0) * DI + d;
    const float* xptr = d_xi  + (size_t)(b * L_SEQ + t0) * DI + d;
#pragma unroll 2
    for (int t = 0; t < tlen; t++) {
        float dv = dptr[(size_t)t * DI];
        float xv = xptr[(size_t)t * DI];
        float u = dv * xv;
#pragma unroll
        for (int n = 0; n < DS; n++) {
            float a = fast_exp(dv * A[n]);
            h[n] = fmaf(h[n], a, u * Bsh[t * DS + n]);
            ap[n] *= a;
        }
    }
    size_t base = ((size_t)((b * DI + d) * NCH + c)) * DS;
#pragma unroll
    for (int n = 0; n < DS; n++) { d_Aagg[base + n] = ap[n]; d_Hagg[base + n] = h[n]; }
}

// ---------------- phase 2: sequential combine over chunks ----------------
__global__ void scan_p2()
{
    int idx = blockIdx.x * blockDim.x + threadIdx.x;   // b*DI + d
    if (idx >= BSZ * DI) return;
    float h[DS];
#pragma unroll
    for (int n = 0; n < DS; n++) h[n] = 0.0f;
    for (int c = 0; c < NCH; c++) {
        size_t base = ((size_t)(idx * NCH + c)) * DS;
#pragma unroll
        for (int n = 0; n < DS; n++) {
            d_Hst[base + n] = h[n];
            h[n] = fmaf(d_Aagg[base + n], h[n], d_Hagg[base + n]);
        }
    }
}

// ---------------- phase 3: replay with true h0, fuse gate ----------------
__global__ __launch_bounds__(128) void scan_p3(const float* __restrict__ Dpl)
{
    int blk = blockIdx.x;
    int dq = blk & 3;
    int rest = blk >> 2;
    int c = rest % NCH;
    int b = rest / NCH;
    int d = dq * 128 + threadIdx.x;
    int t0 = c * CHUNK;
    int tlen = min(CHUNK, L_SEQ - t0);

    __shared__ float Bsh[CHUNK * DS];
    __shared__ float Csh[CHUNK * DS];
    for (int i = threadIdx.x; i < tlen * DS; i += blockDim.x) {
        int t = i >> 4, n = i & 15;
        size_t r = (size_t)(b * L_SEQ + t0 + t) * 48;
        Bsh[i] = d_dbc[r + 16 + n];
        Csh[i] = d_dbc[r + 32 + n];
    }
    __syncthreads();

    float A[DS], h[DS];
    size_t base = ((size_t)((b * DI + d) * NCH + c)) * DS;
#pragma unroll
    for (int n = 0; n < DS; n++) { A[n] = d_Aneg[d * DS + n]; h[n] = d_Hst[base + n]; }

    float Dd = Dpl[d];
    const float* dptr = d_del + (size_t)(b * L_SEQ + t0) * DI + d;
    const float* xptr = d_xi  + (size_t)(b * L_SEQ + t0) * DI + d;
#pragma unroll 2
    for (int t = 0; t < tlen; t++) {
        float dv = dptr[(size_t)t * DI];
        float xv = xptr[(size_t)t * DI];
        float u = dv * xv;
        float y = 0.0f;
#pragma unroll
        for (int n = 0; n < DS; n++) {
            float a = fast_exp(dv * A[n]);
            h[n] = fmaf(h[n], a, u * Bsh[t * DS + n]);
            y = fmaf(h[n], Csh[t * DS + n], y);
        }
        float yv = fmaf(xv, Dd, y);
        size_t grow = (size_t)(b * L_SEQ + t0 + t);
        float zv = d_xz[grow * 1024 + DI + d];
        d_y[grow * DI + d] = yv * zv * sigm(zv);
    }
}

// ---------------- batch norm over (B,L) ----------------------------------
__global__ void bn_partial()
{
    int c = threadIdx.x;
    int bi = blockIdx.x;
    float s = 0.0f, q = 0.0f;
    for (int r = bi; r < NROWS; r += gridDim.x) {
        float v = d_xx[(size_t)r * DM + c];
        s += v; q += v * v;
    }
    d_pS[bi * DM + c] = s;
    d_pQ[bi * DM + c] = q;
}

__global__ void bn_final(const float* __restrict__ bn_g, const float* __restrict__ bn_b)
{
    int c = threadIdx.x;
    float s = 0.0f, q = 0.0f;
    for (int i = 0; i < 128; i++) { s += d_pS[i * DM + c]; q += d_pQ[i * DM + c]; }
    float mu = s * (1.0f / (float)NROWS);
    float var = q * (1.0f / (float)NROWS) - mu * mu;
    float al = bn_g[c] / sqrtf(var + EPSF);
    d_alpha[c] = al;
    d_beta[c] = bn_b[c] - mu * al;
}

__global__ void bn_apply(float* __restrict__ out, int out_size)
{
    int i = blockIdx.x * blockDim.x + threadIdx.x;
    if (i < NXX) {
        int c = i & 255;
        out[i] = d_xx[i] * d_alpha[c] + d_beta[c];
    } else if (i < out_size) {
        out[i] = 1024.0f;   // second tuple element: 4*N
    }
}

// ---------------- host orchestration -------------------------------------
extern "C" void kernel_launch(void* const* d_in, const int* in_sizes, int n_in,
                              void* d_out, int out_size)
{
    const float* x        = (const float*)d_in[0];
    const float* skip     = (const float*)d_in[1];
    const float* exp_w    = (const float*)d_in[2];
    const float* ln_g     = (const float*)d_in[3];
    const float* ln_b     = (const float*)d_in[4];
    const float* cls_w    = (const float*)d_in[5];
    const float* cls_b    = (const float*)d_in[6];
    const float* in_projw = (const float*)d_in[7];
    const float* conv_w   = (const float*)d_in[8];
    const float* conv_b   = (const float*)d_in[9];
    const float* xproj_w  = (const float*)d_in[10];
    const float* dt_w     = (const float*)d_in[11];
    const float* dt_b     = (const float*)d_in[12];
    const float* A_log    = (const float*)d_in[13];
    const float* Dp       = (const float*)d_in[14];
    const float* out_w    = (const float*)d_in[15];
    const float* bn_g     = (const float*)d_in[16];
    const float* bn_b     = (const float*)d_in[17];

    float *pE, *pXX, *pXZ, *pXI, *pDBC, *pY;
    cudaGetSymbolAddress((void**)&pE,   d_E);
    cudaGetSymbolAddress((void**)&pXX,  d_xx);
    cudaGetSymbolAddress((void**)&pXZ,  d_xz);
    cudaGetSymbolAddress((void**)&pXI,  d_xi);
    cudaGetSymbolAddress((void**)&pDBC, d_dbc);
    cudaGetSymbolAddress((void**)&pY,   d_y);

    // 1. patch-expand GEMM per batch (skips the cls row of x)
    for (int b = 0; b < BSZ; b++) {
        sgemm_tn<<<dim3(16, 16), 256>>>(
            x + ((size_t)b * 1025 + 1) * 512, exp_w,
            pE + (size_t)b * 1024 * 1024, 1024, 1024, 512);
    }
    // 2. layernorm + scatter + skip; cls token
    expand_ln<<<8192, 256>>>(skip, ln_g, ln_b);
    cls_kernel<<<BSZ, 256>>>(x, cls_w, cls_b, skip);

    // 3. mamba layers
    for (int layer = 0; layer < 2; layer++) {
        const float* Wi   = in_projw + (size_t)layer * 1024 * 256;
        const float* cw   = conv_w   + (size_t)layer * 512 * 4;
        const float* cb   = conv_b   + (size_t)layer * 512;
        const float* Wx   = xproj_w  + (size_t)layer * 48 * 512;
        const float* Wdt  = dt_w     + (size_t)layer * 512 * 16;
        const float* bdt  = dt_b     + (size_t)layer * 512;
        const float* Alog = A_log    + (size_t)layer * 512 * 16;
        const float* Dpl  = Dp       + (size_t)layer * 512;
        const float* Wo   = out_w    + (size_t)layer * 256 * 512;

        sgemm_tn<<<dim3(16, (NROWS + 63) / 64), 256>>>(pXX, Wi, pXZ, NROWS, 1024, 256);
        conv_silu<<<(NROWS * DI + 255) / 256, 256>>>(cw, cb);
        sgemm_tn<<<dim3(1, (NROWS + 63) / 64), 256>>>(pXI, Wx, pDBC, NROWS, 48, 512);
        delta_kernel<<<NROWS, 512>>>(Wdt, bdt);
        prep_aneg<<<(DI * DS + 255) / 256, 256>>>(Alog);
        scan_p1<<<BSZ * NCH * 4, 128>>>();
        scan_p2<<<4, 256>>>();
        scan_p3<<<BSZ * NCH * 4, 128>>>(Dpl);
        sgemm_tn<<<dim3(4, (NROWS + 63) / 64), 256>>>(pY, Wo, pXX, NROWS, 256, 512);
    }

    // 4. batch norm -> output (+tuple tail if present)
    bn_partial<<<128, 256>>>();
    bn_final<<<1, 256>>>(bn_g, bn_b);
    int total = (out_size > NXX) ? out_size : NXX;
    bn_apply<<<(total + 255) / 256, 256>>>((float*)d_out, out_size);
}

// round 2
// speedup vs baseline: 1.0778x; 1.0778x over previous
#include <cuda_runtime.h>
#include <math.h>
#include <stdint.h>

// ---------------- problem constants ----------------
#define BSZ   2
#define L_SEQ 4097
#define NROWS (BSZ * L_SEQ)      // 8194
#define DM    256                 // d_model
#define DI    512                 // d_inner
#define DS    16                  // d_state
#define CHUNK 128
#define NCH   33                  // ceil(4097/128)
#define NXX   (NROWS * DM)        // 2,097,664
#define EPSF  1e-5f

// ---------------- scratch (static device globals; no runtime alloc) ------
__device__ float d_E[(size_t)BSZ * 1024 * 1024];        // expand GEMM out
__device__ float d_xx[(size_t)NROWS * DM];              // sequence activations
__device__ float d_xz[(size_t)NROWS * 1024];            // in_proj out
__device__ float d_xi[(size_t)NROWS * DI];              // conv+silu out
__device__ float d_dbc[(size_t)NROWS * 48];             // x_proj out
__device__ float d_del[(size_t)NROWS * DI];             // delta
__device__ float d_y[(size_t)NROWS * DI];               // gated scan out
__device__ float d_Aneg[DI * DS];
__device__ float d_Aagg[(size_t)BSZ * DI * NCH * DS];
__device__ float d_Hagg[(size_t)BSZ * DI * NCH * DS];
__device__ float d_Hst [(size_t)BSZ * DI * NCH * DS];
__device__ float d_pS[128 * DM];
__device__ float d_pQ[128 * DM];
__device__ float d_alpha[DM];
__device__ float d_beta[DM];

// ---------------- fast math (FMA-only exp; avoids MUFU throughput wall) --
static __device__ __forceinline__ float fast_exp(float x) {
    float y = x * 1.4426950408889634f;          // log2(e)
    y = fminf(fmaxf(y, -125.0f), 125.0f);
    float k = rintf(y);
    float g = (y - k) * 0.6931471805599453f;    // |g| <= 0.3466
    float p = 1.3888889e-3f;
    p = fmaf(p, g, 8.3333333e-3f);
    p = fmaf(p, g, 4.1666667e-2f);
    p = fmaf(p, g, 1.6666667e-1f);
    p = fmaf(p, g, 0.5f);
    p = fmaf(p, g, 1.0f);
    p = fmaf(p, g, 1.0f);
    int ki = (int)k;
    float sc = __int_as_float((ki + 127) << 23);
    return p * sc;
}
static __device__ __forceinline__ float sigm(float x) {
    return 1.0f / (1.0f + fast_exp(-x));
}

// ---------------- big SGEMM: C[M,N] = A[M,K] @ W[N,K]^T ------------------
// 128x128 tile, 256 threads, 8x8 micro-tile, double-buffered smem.
// K % 16 == 0, N % 128 == 0 required. gridDim.z batches via strides.
__global__ __launch_bounds__(256) void sgemm128(
    const float* __restrict__ A, const float* __restrict__ W,
    float* __restrict__ C, int M, int N, int K,
    long Abs, long Cbs)
{
    A += (size_t)blockIdx.z * Abs;
    C += (size_t)blockIdx.z * Cbs;
    __shared__ float As[2][16][128];
    __shared__ float Ws[2][16][128];
    int tid = threadIdx.x;
    int tx = tid & 15, ty = tid >> 4;
    int row0 = blockIdx.y * 128, col0 = blockIdx.x * 128;

    float acc[8][8];
#pragma unroll
    for (int i = 0; i < 8; i++)
#pragma unroll
        for (int j = 0; j < 8; j++) acc[i][j] = 0.0f;

    // loader mapping: 512 float4 per tile per matrix; 2 per thread
    int i0 = tid, i1 = tid + 256;
    int r0 = i0 >> 2, kq0 = (i0 & 3) * 4;
    int r1 = i1 >> 2, kq1 = (i1 & 3) * 4;

    // ---- stage 0 direct load ----
    {
        float4 va0 = make_float4(0.f,0.f,0.f,0.f), va1 = va0, vw0 = va0, vw1 = va0;
        if (row0 + r0 < M) va0 = *(const float4*)(A + (size_t)(row0 + r0) * K + kq0);
        if (row0 + r1 < M) va1 = *(const float4*)(A + (size_t)(row0 + r1) * K + kq1);
        vw0 = *(const float4*)(W + (size_t)(col0 + r0) * K + kq0);
        vw1 = *(const float4*)(W + (size_t)(col0 + r1) * K + kq1);
        As[0][kq0+0][r0]=va0.x; As[0][kq0+1][r0]=va0.y; As[0][kq0+2][r0]=va0.z; As[0][kq0+3][r0]=va0.w;
        As[0][kq1+0][r1]=va1.x; As[0][kq1+1][r1]=va1.y; As[0][kq1+2][r1]=va1.z; As[0][kq1+3][r1]=va1.w;
        Ws[0][kq0+0][r0]=vw0.x; Ws[0][kq0+1][r0]=vw0.y; Ws[0][kq0+2][r0]=vw0.z; Ws[0][kq0+3][r0]=vw0.w;
        Ws[0][kq1+0][r1]=vw1.x; Ws[0][kq1+1][r1]=vw1.y; Ws[0][kq1+2][r1]=vw1.z; Ws[0][kq1+3][r1]=vw1.w;
    }
    __syncthreads();

    int nst = K >> 4;
    int buf = 0;
    for (int s = 0; s < nst; s++) {
        float4 pa0, pa1, pw0, pw1;
        bool more = (s + 1 < nst);
        if (more) {
            int kc = (s + 1) << 4;
            pa0 = make_float4(0.f,0.f,0.f,0.f); pa1 = pa0;
            if (row0 + r0 < M) pa0 = *(const float4*)(A + (size_t)(row0 + r0) * K + kc + kq0);
            if (row0 + r1 < M) pa1 = *(const float4*)(A + (size_t)(row0 + r1) * K + kc + kq1);
            pw0 = *(const float4*)(W + (size_t)(col0 + r0) * K + kc + kq0);
            pw1 = *(const float4*)(W + (size_t)(col0 + r1) * K + kc + kq1);
        }
#pragma unroll
        for (int kk = 0; kk < 16; kk++) {
            float a[8], w[8];
            *(float4*)(a)   = *(const float4*)(&As[buf][kk][ty*8]);
            *(float4*)(a+4) = *(const float4*)(&As[buf][kk][ty*8+4]);
            *(float4*)(w)   = *(const float4*)(&Ws[buf][kk][tx*8]);
            *(float4*)(w+4) = *(const float4*)(&Ws[buf][kk][tx*8+4]);
#pragma unroll
            for (int i = 0; i < 8; i++)
#pragma unroll
                for (int j = 0; j < 8; j++)
                    acc[i][j] = fmaf(a[i], w[j], acc[i][j]);
        }
        if (more) {
            int nb = buf ^ 1;
            As[nb][kq0+0][r0]=pa0.x; As[nb][kq0+1][r0]=pa0.y; As[nb][kq0+2][r0]=pa0.z; As[nb][kq0+3][r0]=pa0.w;
            As[nb][kq1+0][r1]=pa1.x; As[nb][kq1+1][r1]=pa1.y; As[nb][kq1+2][r1]=pa1.z; As[nb][kq1+3][r1]=pa1.w;
            Ws[nb][kq0+0][r0]=pw0.x; Ws[nb][kq0+1][r0]=pw0.y; Ws[nb][kq0+2][r0]=pw0.z; Ws[nb][kq0+3][r0]=pw0.w;
            Ws[nb][kq1+0][r1]=pw1.x; Ws[nb][kq1+1][r1]=pw1.y; Ws[nb][kq1+2][r1]=pw1.z; Ws[nb][kq1+3][r1]=pw1.w;
            __syncthreads();
            buf = nb;
        }
    }
#pragma unroll
    for (int i = 0; i < 8; i++) {
        int r = row0 + ty * 8 + i;
        if (r < M) {
            float4* cp = (float4*)(C + (size_t)r * N + col0 + tx * 8);
            cp[0] = make_float4(acc[i][0], acc[i][1], acc[i][2], acc[i][3]);
            cp[1] = make_float4(acc[i][4], acc[i][5], acc[i][6], acc[i][7]);
        }
    }
}

// ---------------- small SGEMM (N not mult of 64): x_proj -----------------
__global__ __launch_bounds__(256) void sgemm_tn(
    const float* __restrict__ A, const float* __restrict__ W,
    float* __restrict__ C, int M, int N, int K)
{
    __shared__ float As[16][64];
    __shared__ float Ws[16][64];
    int tid = threadIdx.x;
    int tx = tid & 15, ty = tid >> 4;
    int row0 = blockIdx.y * 64, col0 = blockIdx.x * 64;
    float acc[4][4];
#pragma unroll
    for (int i = 0; i < 4; i++)
#pragma unroll
        for (int j = 0; j < 4; j++) acc[i][j] = 0.0f;

    int lr = tid >> 2;
    int lk = (tid & 3) * 4;

    for (int kc = 0; kc < K; kc += 16) {
        float4 va = make_float4(0.f, 0.f, 0.f, 0.f);
        if (row0 + lr < M)
            va = *reinterpret_cast<const float4*>(A + (size_t)(row0 + lr) * K + kc + lk);
        As[lk + 0][lr] = va.x; As[lk + 1][lr] = va.y;
        As[lk + 2][lr] = va.z; As[lk + 3][lr] = va.w;
        float4 vw = make_float4(0.f, 0.f, 0.f, 0.f);
        if (col0 + lr < N)
            vw = *reinterpret_cast<const float4*>(W + (size_t)(col0 + lr) * K + kc + lk);
        Ws[lk + 0][lr] = vw.x; Ws[lk + 1][lr] = vw.y;
        Ws[lk + 2][lr] = vw.z; Ws[lk + 3][lr] = vw.w;
        __syncthreads();
#pragma unroll
        for (int kk = 0; kk < 16; kk++) {
            float a[4], w[4];
            *reinterpret_cast<float4*>(a) = *reinterpret_cast<const float4*>(&As[kk][ty * 4]);
            *reinterpret_cast<float4*>(w) = *reinterpret_cast<const float4*>(&Ws[kk][tx * 4]);
#pragma unroll
            for (int i = 0; i < 4; i++)
#pragma unroll
                for (int j = 0; j < 4; j++)
                    acc[i][j] = fmaf(a[i], w[j], acc[i][j]);
        }
        __syncthreads();
    }
#pragma unroll
    for (int i = 0; i < 4; i++) {
        int r = row0 + ty * 4 + i;
        if (r < M) {
#pragma unroll
            for (int j = 0; j < 4; j++) {
                int c = col0 + tx * 4 + j;
                if (c < N) C[(size_t)r * N + c] = acc[i][j];
            }
        }
    }
}

// ---------------- expand: LN over 256 + spatial scatter + skip -----------
__global__ void expand_ln(const float* __restrict__ skip,
                          const float* __restrict__ ln_g,
                          const float* __restrict__ ln_b)
{
    int idx = blockIdx.x;
    int q = idx & 3;
    int src = idx >> 2;
    int b = src >> 10;
    int rowb = src & 1023;
    int t = rowb >> 8;
    int n = rowb & 255;
    int hh = n >> 4, ww = n & 15;
    int s1 = q >> 1, s2 = q & 1;
    int p = ((hh * 2 + s1) * 16 + ww) * 2 + s2;
    int l = 1 + t * 1024 + p;
    int tid = threadIdx.x;
    int lane = tid & 31, wid = tid >> 5;

    float v = d_E[(size_t)src * 1024 + q * 256 + tid];
    float s = v, qq = v * v;
#pragma unroll
    for (int o = 16; o; o >>= 1) {
        s  += __shfl_xor_sync(0xffffffffu, s, o);
        qq += __shfl_xor_sync(0xffffffffu, qq, o);
    }
    __shared__ float ws[8], wq[8];
    if (lane == 0) { ws[wid] = s; wq[wid] = qq; }
    __syncthreads();
    if (wid == 0) {
        float a = (lane < 8) ? ws[lane] : 0.0f;
        float c = (lane < 8) ? wq[lane] : 0.0f;
#pragma unroll
        for (int o = 4; o; o >>= 1) {
            a += __shfl_xor_sync(0xffffffffu, a, o);
            c += __shfl_xor_sync(0xffffffffu, c, o);
        }
        if (lane == 0) { ws[0] = a; wq[0] = c; }
    }
    __syncthreads();
    float mu = ws[0] * (1.0f / 256.0f);
    float var = wq[0] * (1.0f / 256.0f) - mu * mu;
    float outv = (v - mu) * rsqrtf(var + EPSF) * ln_g[tid] + ln_b[tid];
    size_t grow = (size_t)(b * L_SEQ + l);
    d_xx[grow * DM + tid] = outv + skip[grow * DM + tid];
}

// ---------------- cls token: warp per output -----------------------------
__global__ void cls_kernel(const float* __restrict__ x,
                           const float* __restrict__ cls_w,
                           const float* __restrict__ cls_b,
                           const float* __restrict__ skip)
{
    int gw = blockIdx.x * 8 + (threadIdx.x >> 5);   // 0 .. 511
    int b = gw >> 8, c = gw & 255;
    int lane = threadIdx.x & 31;
    const float* xr = x + (size_t)b * 1025 * 512;
    float s = 0.0f;
#pragma unroll 4
    for (int k = lane; k < 512; k += 32)
        s = fmaf(xr[k], cls_w[(size_t)c * 512 + k], s);
#pragma unroll
    for (int o = 16; o; o >>= 1) s += __shfl_xor_sync(0xffffffffu, s, o);
    if (lane == 0) {
        size_t grow = (size_t)b * L_SEQ;
        d_xx[grow * DM + c] = s + cls_b[c] + skip[grow * DM + c];
    }
}

// ---------------- depthwise causal conv4 + silu --------------------------
__global__ void conv_silu(const float* __restrict__ cw, const float* __restrict__ cb)
{
    int idx = blockIdx.x * blockDim.x + threadIdx.x;
    if (idx >= NROWS * DI) return;
    int row = idx >> 9;
    int d = idx & 511;
    int b = row / L_SEQ;
    int l = row - b * L_SEQ;
    float acc = cb[d];
#pragma unroll
    for (int k = 0; k < 4; k++) {
        int ls = l + k - 3;
        if (ls >= 0)
            acc = fmaf(cw[d * 4 + k], d_xz[(size_t)(b * L_SEQ + ls) * 1024 + d], acc);
    }
    d_xi[(size_t)row * DI + d] = acc * sigm(acc);
}

// ---------------- delta = softplus(dt @ Wdt^T + bdt) ---------------------
__global__ void delta_kernel(const float* __restrict__ Wdt, const float* __restrict__ bdt)
{
    int row = blockIdx.x;
    int dd = threadIdx.x;
    __shared__ float dt[16];
    if (dd < 16) dt[dd] = d_dbc[(size_t)row * 48 + dd];
    __syncthreads();
    float s = bdt[dd];
#pragma unroll
    for (int r = 0; r < 16; r++) s = fmaf(dt[r], Wdt[dd * 16 + r], s);
    float del = (s > 20.0f) ? s : log1pf(fast_exp(s));
    d_del[(size_t)row * DI + dd] = del;
}

// ---------------- A = -exp(A_log) ----------------------------------------
__global__ void prep_aneg(const float* __restrict__ Alog)
{
    int i = blockIdx.x * blockDim.x + threadIdx.x;
    if (i < DI * DS) d_Aneg[i] = -expf(Alog[i]);
}

// ---------------- chunked scan phase 1 -----------------------------------
__global__ __launch_bounds__(128) void scan_p1()
{
    int blk = blockIdx.x;
    int dq = blk & 3;
    int rest = blk >> 2;
    int c = rest % NCH;
    int b = rest / NCH;
    int d = dq * 128 + threadIdx.x;
    int t0 = c * CHUNK;
    int tlen = min(CHUNK, L_SEQ - t0);

    __shared__ float Bsh[CHUNK * DS];
    for (int i = threadIdx.x; i < tlen * DS; i += blockDim.x) {
        int t = i >> 4, n = i & 15;
        Bsh[i] = d_dbc[(size_t)(b * L_SEQ + t0 + t) * 48 + 16 + n];
    }
    __syncthreads();

    float A[DS], h[DS], ap[DS];
#pragma unroll
    for (int n = 0; n < DS; n++) {
        A[n] = d_Aneg[d * DS + n]; h[n] = 0.0f; ap[n] = 1.0f;
    }
    const float* dptr = d_del + (size_t)(b * L_SEQ + t0) * DI + d;
    const float* xptr = d_xi  + (size_t)(b * L_SEQ + t0) * DI + d;
#pragma unroll 2
    for (int t = 0; t < tlen; t++) {
        float dv = dptr[(size_t)t * DI];
        float xv = xptr[(size_t)t * DI];
        float u = dv * xv;
#pragma unroll
        for (int n = 0; n < DS; n++) {
            float a = fast_exp(dv * A[n]);
            h[n] = fmaf(h[n], a, u * Bsh[t * DS + n]);
            ap[n] *= a;
        }
    }
    size_t base = ((size_t)((b * DI + d) * NCH + c)) * DS;
#pragma unroll
    for (int n = 0; n < DS; n++) { d_Aagg[base + n] = ap[n]; d_Hagg[base + n] = h[n]; }
}

// ---------------- phase 2: sequential combine over chunks ----------------
__global__ void scan_p2()
{
    int idx = blockIdx.x * blockDim.x + threadIdx.x;
    if (idx >= BSZ * DI) return;
    float h[DS];
#pragma unroll
    for (int n = 0; n < DS; n++) h[n] = 0.0f;
    for (int c = 0; c < NCH; c++) {
        size_t base = ((size_t)(idx * NCH + c)) * DS;
#pragma unroll
        for (int n = 0; n < DS; n++) {
            d_Hst[base + n] = h[n];
            h[n] = fmaf(d_Aagg[base + n], h[n], d_Hagg[base + n]);
        }
    }
}

// ---------------- phase 3: replay with true h0, fuse gate ----------------
__global__ __launch_bounds__(128) void scan_p3(const float* __restrict__ Dpl)
{
    int blk = blockIdx.x;
    int dq = blk & 3;
    int rest = blk >> 2;
    int c = rest % NCH;
    int b = rest / NCH;
    int d = dq * 128 + threadIdx.x;
    int t0 = c * CHUNK;
    int tlen = min(CHUNK, L_SEQ - t0);

    __shared__ float Bsh[CHUNK * DS];
    __shared__ float Csh[CHUNK * DS];
    for (int i = threadIdx.x; i < tlen * DS; i += blockDim.x) {
        int t = i >> 4, n = i & 15;
        size_t r = (size_t)(b * L_SEQ + t0 + t) * 48;
        Bsh[i] = d_dbc[r + 16 + n];
        Csh[i] = d_dbc[r + 32 + n];
    }
    __syncthreads();

    float A[DS], h[DS];
    size_t base = ((size_t)((b * DI + d) * NCH + c)) * DS;
#pragma unroll
    for (int n = 0; n < DS; n++) { A[n] = d_Aneg[d * DS + n]; h[n] = d_Hst[base + n]; }

    float Dd = Dpl[d];
    const float* dptr = d_del + (size_t)(b * L_SEQ + t0) * DI + d;
    const float* xptr = d_xi  + (size_t)(b * L_SEQ + t0) * DI + d;
#pragma unroll 2
    for (int t = 0; t < tlen; t++) {
        float dv = dptr[(size_t)t * DI];
        float xv = xptr[(size_t)t * DI];
        float u = dv * xv;
        float y = 0.0f;
#pragma unroll
        for (int n = 0; n < DS; n++) {
            float a = fast_exp(dv * A[n]);
            h[n] = fmaf(h[n], a, u * Bsh[t * DS + n]);
            y = fmaf(h[n], Csh[t * DS + n], y);
        }
        float yv = fmaf(xv, Dd, y);
        size_t grow = (size_t)(b * L_SEQ + t0 + t);
        float zv = d_xz[grow * 1024 + DI + d];
        d_y[grow * DI + d] = yv * zv * sigm(zv);
    }
}

// ---------------- batch norm over (B,L) ----------------------------------
__global__ void bn_partial()
{
    int c = threadIdx.x;
    int bi = blockIdx.x;
    float s = 0.0f, q = 0.0f;
    for (int r = bi; r < NROWS; r += gridDim.x) {
        float v = d_xx[(size_t)r * DM + c];
        s += v; q += v * v;
    }
    d_pS[bi * DM + c] = s;
    d_pQ[bi * DM + c] = q;
}

__global__ void bn_final(const float* __restrict__ bn_g, const float* __restrict__ bn_b)
{
    int c = threadIdx.x;
    float s = 0.0f, q = 0.0f;
    for (int i = 0; i < 128; i++) { s += d_pS[i * DM + c]; q += d_pQ[i * DM + c]; }
    float mu = s * (1.0f / (float)NROWS);
    float var = q * (1.0f / (float)NROWS) - mu * mu;
    float al = bn_g[c] / sqrtf(var + EPSF);
    d_alpha[c] = al;
    d_beta[c] = bn_b[c] - mu * al;
}

__global__ void bn_apply(float* __restrict__ out, int out_size)
{
    int i = blockIdx.x * blockDim.x + threadIdx.x;
    if (i < NXX) {
        int c = i & 255;
        out[i] = d_xx[i] * d_alpha[c] + d_beta[c];
    } else if (i < out_size) {
        out[i] = 1024.0f;
    }
}

// ---------------- host orchestration -------------------------------------
extern "C" void kernel_launch(void* const* d_in, const int* in_sizes, int n_in,
                              void* d_out, int out_size)
{
    const float* x        = (const float*)d_in[0];
    const float* skip     = (const float*)d_in[1];
    const float* exp_w    = (const float*)d_in[2];
    const float* ln_g     = (const float*)d_in[3];
    const float* ln_b     = (const float*)d_in[4];
    const float* cls_w    = (const float*)d_in[5];
    const float* cls_b    = (const float*)d_in[6];
    const float* in_projw = (const float*)d_in[7];
    const float* conv_w   = (const float*)d_in[8];
    const float* conv_b   = (const float*)d_in[9];
    const float* xproj_w  = (const float*)d_in[10];
    const float* dt_w     = (const float*)d_in[11];
    const float* dt_b     = (const float*)d_in[12];
    const float* A_log    = (const float*)d_in[13];
    const float* Dp       = (const float*)d_in[14];
    const float* out_w    = (const float*)d_in[15];
    const float* bn_g     = (const float*)d_in[16];
    const float* bn_b     = (const float*)d_in[17];

    float *pE, *pXX, *pXZ, *pXI, *pDBC, *pY;
    cudaGetSymbolAddress((void**)&pE,   d_E);
    cudaGetSymbolAddress((void**)&pXX,  d_xx);
    cudaGetSymbolAddress((void**)&pXZ,  d_xz);
    cudaGetSymbolAddress((void**)&pXI,  d_xi);
    cudaGetSymbolAddress((void**)&pDBC, d_dbc);
    cudaGetSymbolAddress((void**)&pY,   d_y);

    // 1. patch-expand GEMM: both batches in one launch via gridDim.z
    sgemm128<<<dim3(8, 8, 2), 256>>>(
        x + 512, exp_w, pE, 1024, 1024, 512,
        (long)1025 * 512, (long)1024 * 1024);

    // 2. layernorm + scatter + skip; cls token
    expand_ln<<<8192, 256>>>(skip, ln_g, ln_b);
    cls_kernel<<<64, 256>>>(x, cls_w, cls_b, skip);

    // 3. mamba layers
    for (int layer = 0; layer < 2; layer++) {
        const float* Wi   = in_projw + (size_t)layer * 1024 * 256;
        const float* cw   = conv_w   + (size_t)layer * 512 * 4;
        const float* cb   = conv_b   + (size_t)layer * 512;
        const float* Wx   = xproj_w  + (size_t)layer * 48 * 512;
        const float* Wdt  = dt_w     + (size_t)layer * 512 * 16;
        const float* bdt  = dt_b     + (size_t)layer * 512;
        const float* Alog = A_log    + (size_t)layer * 512 * 16;
        const float* Dpl  = Dp       + (size_t)layer * 512;
        const float* Wo   = out_w    + (size_t)layer * 256 * 512;

        sgemm128<<<dim3(8, (NROWS + 127) / 128, 1), 256>>>(pXX, Wi, pXZ, NROWS, 1024, 256, 0, 0);
        conv_silu<<<(NROWS * DI + 255) / 256, 256>>>(cw, cb);
        sgemm_tn<<<dim3(1, (NROWS + 63) / 64), 256>>>(pXI, Wx, pDBC, NROWS, 48, 512);
        delta_kernel<<<NROWS, 512>>>(Wdt, bdt);
        prep_aneg<<<(DI * DS + 255) / 256, 256>>>(Alog);
        scan_p1<<<BSZ * NCH * 4, 128>>>();
        scan_p2<<<4, 256>>>();
        scan_p3<<<BSZ * NCH * 4, 128>>>(Dpl);
        sgemm128<<<dim3(2, (NROWS + 127) / 128, 1), 256>>>(pY, Wo, pXX, NROWS, 256, 512, 0, 0);
    }

    // 4. batch norm -> output
    bn_partial<<<128, 256>>>();
    bn_final<<<1, 256>>>(bn_g, bn_b);
    int total = (out_size > NXX) ? out_size : NXX;
    bn_apply<<<(total + 255) / 256, 256>>>((float*)d_out, out_size);
}